// round 15
// baseline (speedup 1.0000x reference)
#include <cuda_runtime.h>
#include <cstdint>
#include <math.h>

#define BB 8
#define CC 8
#define HH 256
#define WW 512
#define PLANE (HH*WW)
#define NPIX (BB*PLANE)
#define OUTH 8                              /* output rows per CTA per double-step */
#define D1R (OUTH+2)                        /* 10 intermediate rows */
#define IR  (OUTH+4)                        /* 12 input rows */
#define TX 128
#define SROW 136
#define GRID_I (BB*(HH/OUTH)*(WW/TX))       /* 1024 */
#define NSTEPS 8                            /* 8 double-steps = 16 iters */
#define FULLMASK 0xffffffffu

#define SG  (CC*IR*SROW)                    /* 13056 floats */
#define SD  (IR*SROW)                       /* 1632 */
#define SD1 (D1R*SROW)                      /* 1360 */
#define SMEM_FLOATS (16 + SG + SD + SD1)
#define SMEM_BYTES (SMEM_FLOATS*4)          /* 64,256 B -> 3 CTAs/SM */

// Scratch (allocation-free).
__device__ float d_bufA[NPIX];              // 4 MB
__device__ float d_bufB[NPIX];              // 4 MB
__device__ float r_buf[(size_t)BB*CC*PLANE];// 32 MB: 1/(3x3 sum |g|), iter-invariant

// ---------------------------------------------------------------------------
// Init: d0 = sparse > 0 ? sparse : blur
// ---------------------------------------------------------------------------
__global__ __launch_bounds__(256) void init_kernel(
    const float* __restrict__ blur,
    const float* __restrict__ sparse)
{
    const int i = blockIdx.x * 256 + threadIdx.x;
    const float4 s = reinterpret_cast<const float4*>(sparse)[i];
    float4 v       = reinterpret_cast<const float4*>(blur)[i];
    v.x = (s.x > 0.f) ? s.x : v.x;
    v.y = (s.y > 0.f) ? s.y : v.y;
    v.z = (s.z > 0.f) ? s.z : v.z;
    v.w = (s.w > 0.f) ? s.w : v.w;
    reinterpret_cast<float4*>(d_bufA)[i] = v;
}

// ---------------------------------------------------------------------------
// Pre-pass (once): r = 1/(3x3 in-image sum of |guid|). Rolling 8-row bands,
// channel-parallel across blocks. 64 MB IO total.
// ---------------------------------------------------------------------------
__global__ __launch_bounds__(64) void rpre_kernel(const float* __restrict__ guid)
{
    const int lane  = threadIdx.x & 31;
    const int warp  = threadIdx.x >> 5;
    const int c     = blockIdx.x >> 9;         // 0..7
    const int inner = blockIdx.x & 511;
    const int band  = inner >> 1;              // 0..255 (8-row bands)
    const int chunk = inner & 1;
    const int x0    = chunk * 256 + warp * 128 + lane * 4;
    const int b     = (band * 8) / HH;
    const int y0    = (band * 8) % HH;

    const float* gin  = guid  + ((size_t)(b * CC + c)) * PLANE;
    float*       rout = r_buf + ((size_t)(b * CC + c)) * PLANE;

    float4 rsp = make_float4(0.f,0.f,0.f,0.f);
    float4 rsc = make_float4(0.f,0.f,0.f,0.f);

    #pragma unroll
    for (int i = 0; i < 10; i++) {
        const int  ry    = y0 - 1 + i;
        const bool valid = (ry >= 0) && (ry < HH);

        float4 ga = make_float4(0.f,0.f,0.f,0.f);
        if (valid) {
            const float4 gv = *reinterpret_cast<const float4*>(gin + (size_t)ry * WW + x0);
            ga.x = fabsf(gv.x); ga.y = fabsf(gv.y);
            ga.z = fabsf(gv.z); ga.w = fabsf(gv.w);
        }
        float gm1 = __shfl_up_sync  (FULLMASK, ga.w, 1);
        float gp4 = __shfl_down_sync(FULLMASK, ga.x, 1);
        if (lane == 0)  gm1 = (valid && x0 > 0)      ? fabsf(gin[(size_t)ry * WW + x0 - 1]) : 0.f;
        if (lane == 31) gp4 = (valid && x0 + 4 < WW) ? fabsf(gin[(size_t)ry * WW + x0 + 4]) : 0.f;

        float4 rsn;
        {
            const float s01 = ga.x + ga.y, s12 = ga.y + ga.z, s23 = ga.z + ga.w;
            rsn.x = gm1 + s01; rsn.y = s01 + ga.z;
            rsn.z = s12 + ga.w; rsn.w = s23 + gp4;
        }
        if (i >= 2) {
            const int yo = y0 + i - 2;
            float4 rv;
            rv.x = 1.0f / (rsp.x + rsc.x + rsn.x);
            rv.y = 1.0f / (rsp.y + rsc.y + rsn.y);
            rv.z = 1.0f / (rsp.z + rsc.z + rsn.z);
            rv.w = 1.0f / (rsp.w + rsc.w + rsn.w);
            *reinterpret_cast<float4*>(rout + (size_t)yo * WW + x0) = rv;
        }
        rsp = rsc; rsc = rsn;
    }
}

// ---------------------------------------------------------------------------
// TWO CSPN steps per launch. Denominators come from precomputed r_buf, so the
// phases are numerator-only: out = (3x3 sum g*d) * r, then max over channels.
// ---------------------------------------------------------------------------
__global__ __launch_bounds__(256, 3) void double_kernel(
    int src_sel,
    float* __restrict__ dst_ext,
    const float* __restrict__ guid,
    const float* __restrict__ sparse)
{
    extern __shared__ float smem[];
    float* sg  = smem + 16;                 // [CC][IR][SROW]
    float* sdm = sg + SG;                   // [IR][SROW]
    float* sd1 = sdm + SD;                  // [D1R][SROW]
    const unsigned mbar = (unsigned)__cvta_generic_to_shared(smem);

    const int tid  = threadIdx.x;
    const int lane = tid & 31;
    const int wid  = tid >> 5;
    const int bid  = blockIdx.x;
    const int xc   = bid & 3;
    const int yb   = (bid >> 2) & 31;
    const int b    = bid >> 7;
    const int x0   = xc * TX;
    const int y0   = yb * OUTH;

    const float* dsrc  = src_sel ? d_bufB : d_bufA;
    float*       ddst  = dst_ext ? dst_ext : (src_sel ? d_bufA : d_bufB);
    const float* dsb   = dsrc   + (size_t)b * PLANE;
    const float* spb   = sparse + (size_t)b * PLANE;
    float*       ddb   = ddst   + (size_t)b * PLANE;
    const float* gbase = guid   + ((size_t)(b * CC)) * PLANE;
    const float* rbase = r_buf  + ((size_t)(b * CC)) * PLANE;

    const bool left  = (x0 == 0);
    const bool right = (x0 + TX >= WW);
    const int  src_c0  = left ? 0 : (x0 - 4);
    const int  dst_off = left ? 4 : 0;
    const unsigned cpy_b = (left || right) ? 528u : 544u;
    const int top = (y0 == 0)          ? 2 : 0;
    const int bot = (y0 + OUTH == HH)  ? 2 : 0;

    if (tid == 0)
        asm volatile("mbarrier.init.shared.b64 [%0], %1;" :: "r"(mbar), "r"(1u) : "memory");
    __syncthreads();
    if (tid == 0) {
        const unsigned tx = (unsigned)(CC * (IR - top - bot) + IR) * cpy_b;
        asm volatile("mbarrier.arrive.expect_tx.shared.b64 _, [%0], %1;"
                     :: "r"(mbar), "r"(tx) : "memory");
    }
    __syncthreads();

    // ---- issue bulk row copies: 8 g channels x in-image rows + 12 d rows ----
    if (tid < (CC + 1) * IR) {
        const int cc = tid / IR;
        const int r  = tid % IR;
        const int ry = y0 - 2 + r;
        if (cc < CC) {
            if (ry >= 0 && ry < HH) {
                const float* src = gbase + (size_t)cc * PLANE + (size_t)ry * WW + src_c0;
                const unsigned dsm_ = (unsigned)__cvta_generic_to_shared(
                                          sg + (cc * IR + r) * SROW + dst_off);
                asm volatile(
                    "cp.async.bulk.shared::cta.global.mbarrier::complete_tx::bytes "
                    "[%0], [%1], %2, [%3];"
                    :: "r"(dsm_), "l"(src), "r"(cpy_b), "r"(mbar) : "memory");
            }
        } else {
            const int ryc = (ry < 0) ? 0 : ((ry >= HH) ? (HH - 1) : ry);
            const float* src = dsb + (size_t)ryc * WW + src_c0;
            const unsigned dsm_ = (unsigned)__cvta_generic_to_shared(
                                      sdm + r * SROW + dst_off);
            asm volatile(
                "cp.async.bulk.shared::cta.global.mbarrier::complete_tx::bytes "
                "[%0], [%1], %2, [%3];"
                :: "r"(dsm_), "l"(src), "r"(cpy_b), "r"(mbar) : "memory");
        }
    }

    // ---- zero out-of-image g rows (band top/bottom) ----
    if (top + bot) {
        const int per = (top + bot) * 34;
        const int nz  = CC * per;
        for (int idx = tid; idx < nz; idx += 256) {
            const int ch  = idx / per;
            const int rem = idx - ch * per;
            const int ri  = rem / 34;
            const int j   = rem - ri * 34;
            const int r   = (ri < top) ? ri : (IR - bot + (ri - top));
            *reinterpret_cast<float4*>(sg + (ch * IR + r) * SROW + 4 * j) =
                make_float4(0.f, 0.f, 0.f, 0.f);
        }
    }
    // ---- zero out-of-image halo cols (left/right tiles) ----
    if ((left || right) && tid < (CC + 1) * IR) {
        const int zc = left ? 0 : 132;
        const int cc = tid / IR;
        const int r  = tid % IR;
        float* p = (cc < CC) ? (sg + (cc * IR + r) * SROW + zc)
                             : (sdm + r * SROW + zc);
        *reinterpret_cast<float4*>(p) = make_float4(0.f, 0.f, 0.f, 0.f);
    }

    // ---- wait for bulk data ----
    {
        unsigned done;
        asm volatile(
            "{\n\t.reg .pred p;\n\t"
            "mbarrier.try_wait.parity.acquire.cta.shared::cta.b64 p, [%1], %2;\n\t"
            "selp.b32 %0, 1, 0, p;\n\t}"
            : "=r"(done) : "r"(mbar), "r"(0u) : "memory");
        if (!done) {
            asm volatile(
                "{\n\t.reg .pred P1;\n\t"
                "WAIT_LOOP_%=:\n\t"
                "mbarrier.try_wait.parity.acquire.cta.shared::cta.b64 P1, [%0], %1, 0x989680;\n\t"
                "@P1 bra.uni WAIT_DONE_%=;\n\t"
                "bra.uni WAIT_LOOP_%=;\n\t"
                "WAIT_DONE_%=:\n\t}"
                :: "r"(mbar), "r"(0u) : "memory");
        }
    }
    __syncthreads();

    const int  sc   = 4 + lane * 4;
    const bool is_l = (lane == 0);
    const bool is_r = (lane == 31);

    // ================= PHASE 1: d1 rows via warp-per-row + shfl halos ========
    #pragma unroll
    for (int r1 = wid; r1 < D1R; r1 += 8) {
        const int  yrow = y0 - 1 + r1;
        const bool rv   = (yrow >= 0) && (yrow < HH);
        const int  yrc  = (yrow < 0) ? 0 : ((yrow >= HH) ? (HH - 1) : yrow);

        float4 dv[3]; float dlf[3], drt[3];
        #pragma unroll
        for (int rr = 0; rr < 3; rr++) {
            const float* dp = sdm + (r1 + rr) * SROW;
            dv[rr] = *reinterpret_cast<const float4*>(dp + sc);
            const float up = __shfl_up_sync  (FULLMASK, dv[rr].w, 1);
            const float dn = __shfl_down_sync(FULLMASK, dv[rr].x, 1);
            dlf[rr] = is_l ? dp[3]   : up;
            drt[rr] = is_r ? dp[132] : dn;
        }
        float mx0 = 0.f, mx1 = 0.f, mx2 = 0.f, mx3 = 0.f;
        #pragma unroll
        for (int ch = 0; ch < CC; ch++) {
            const float* gb = sg + ch * IR * SROW;
            const float4 rw = *reinterpret_cast<const float4*>(
                                  rbase + (size_t)ch * PLANE + (size_t)yrc * WW + x0 + lane * 4);
            float n0=0.f,n1=0.f,n2=0.f,n3=0.f;
            #pragma unroll
            for (int rr = 0; rr < 3; rr++) {
                const float* gp = gb + (r1 + rr) * SROW;
                const float4 gv = *reinterpret_cast<const float4*>(gp + sc);
                const float gup = __shfl_up_sync  (FULLMASK, gv.w, 1);
                const float gdn = __shfl_down_sync(FULLMASK, gv.x, 1);
                const float gl  = is_l ? gp[3]   : gup;
                const float gr_ = is_r ? gp[132] : gdn;
                const float ul = fabsf(gl)   * dlf[rr];
                const float u0 = fabsf(gv.x) * dv[rr].x;
                const float u1 = fabsf(gv.y) * dv[rr].y;
                const float u2 = fabsf(gv.z) * dv[rr].z;
                const float u3 = fabsf(gv.w) * dv[rr].w;
                const float ur = fabsf(gr_)  * drt[rr];
                const float t01 = u0 + u1, t12 = u1 + u2, t23 = u2 + u3;
                n0 += ul + t01; n1 += t01 + u2; n2 += t12 + u3; n3 += t23 + ur;
            }
            mx0 = fmaxf(mx0, n0 * rw.x);
            mx1 = fmaxf(mx1, n1 * rw.y);
            mx2 = fmaxf(mx2, n2 * rw.z);
            mx3 = fmaxf(mx3, n3 * rw.w);
        }
        const float4 s = *reinterpret_cast<const float4*>(
                             spb + (size_t)yrc * WW + x0 + lane * 4);
        float4 o;
        o.x = rv ? ((s.x > 0.f) ? s.x : mx0) : 0.f;
        o.y = rv ? ((s.y > 0.f) ? s.y : mx1) : 0.f;
        o.z = rv ? ((s.z > 0.f) ? s.z : mx2) : 0.f;
        o.w = rv ? ((s.w > 0.f) ? s.w : mx3) : 0.f;
        *reinterpret_cast<float4*>(sd1 + r1 * SROW + sc) = o;
    }

    // ---- tail: d1 edge cols (smem cols 3 and 132), rows 0..9 ----
    if (tid < 2 * D1R) {
        const int r1   = tid >> 1;
        const int colc = (tid & 1) ? 132 : 3;
        const int  yrow = y0 - 1 + r1;
        const bool rv   = (yrow >= 0) && (yrow < HH);
        const int  yrc  = (yrow < 0) ? 0 : ((yrow >= HH) ? (HH - 1) : yrow);
        const int  gx   = x0 - 4 + colc;
        const bool xv   = (gx >= 0) && (gx < WW);
        const int  gxc  = (gx < 0) ? 0 : ((gx >= WW) ? (WW - 1) : gx);

        float mx = 0.f;
        #pragma unroll
        for (int ch = 0; ch < CC; ch++) {
            const float* gb = sg + ch * IR * SROW;
            const float rsc_ = r_buf[((size_t)(b * CC + ch)) * PLANE + (size_t)yrc * WW + gxc];
            float n = 0.f;
            #pragma unroll
            for (int rr = 0; rr < 3; rr++) {
                const float* gp = gb  + (r1 + rr) * SROW;
                const float* dp = sdm + (r1 + rr) * SROW;
                #pragma unroll
                for (int dc = -1; dc <= 1; dc++)
                    n += fabsf(gp[colc + dc]) * dp[colc + dc];
            }
            mx = fmaxf(mx, n * rsc_);
        }
        const float s = spb[(size_t)yrc * WW + gxc];
        sd1[r1 * SROW + colc] = (rv && xv) ? ((s > 0.f) ? s : mx) : 0.f;
    }
    __syncthreads();

    // ================= PHASE 2: output rows via warp-per-row =================
    {
        const int k = wid;
        float4 dv[3]; float dlf[3], drt[3];
        #pragma unroll
        for (int rr = 0; rr < 3; rr++) {
            const float* dp = sd1 + (k + rr) * SROW;
            dv[rr] = *reinterpret_cast<const float4*>(dp + sc);
            const float up = __shfl_up_sync  (FULLMASK, dv[rr].w, 1);
            const float dn = __shfl_down_sync(FULLMASK, dv[rr].x, 1);
            dlf[rr] = is_l ? dp[3]   : up;
            drt[rr] = is_r ? dp[132] : dn;
        }
        float mx0 = 0.f, mx1 = 0.f, mx2 = 0.f, mx3 = 0.f;
        #pragma unroll
        for (int ch = 0; ch < CC; ch++) {
            const float* gb = sg + ch * IR * SROW;
            const float4 rw = *reinterpret_cast<const float4*>(
                                  rbase + (size_t)ch * PLANE + (size_t)(y0 + k) * WW + x0 + lane * 4);
            float n0=0.f,n1=0.f,n2=0.f,n3=0.f;
            #pragma unroll
            for (int rr = 0; rr < 3; rr++) {
                const float* gp = gb + (k + 1 + rr) * SROW;
                const float4 gv = *reinterpret_cast<const float4*>(gp + sc);
                const float gup = __shfl_up_sync  (FULLMASK, gv.w, 1);
                const float gdn = __shfl_down_sync(FULLMASK, gv.x, 1);
                const float gl  = is_l ? gp[3]   : gup;
                const float gr_ = is_r ? gp[132] : gdn;
                const float ul = fabsf(gl)   * dlf[rr];
                const float u0 = fabsf(gv.x) * dv[rr].x;
                const float u1 = fabsf(gv.y) * dv[rr].y;
                const float u2 = fabsf(gv.z) * dv[rr].z;
                const float u3 = fabsf(gv.w) * dv[rr].w;
                const float ur = fabsf(gr_)  * drt[rr];
                const float t01 = u0 + u1, t12 = u1 + u2, t23 = u2 + u3;
                n0 += ul + t01; n1 += t01 + u2; n2 += t12 + u3; n3 += t23 + ur;
            }
            mx0 = fmaxf(mx0, n0 * rw.x);
            mx1 = fmaxf(mx1, n1 * rw.y);
            mx2 = fmaxf(mx2, n2 * rw.z);
            mx3 = fmaxf(mx3, n3 * rw.w);
        }
        const size_t off = (size_t)(y0 + k) * WW + x0 + lane * 4;
        const float4 s = *reinterpret_cast<const float4*>(spb + off);
        float4 o;
        o.x = (s.x > 0.f) ? s.x : mx0;
        o.y = (s.y > 0.f) ? s.y : mx1;
        o.z = (s.z > 0.f) ? s.z : mx2;
        o.w = (s.w > 0.f) ? s.w : mx3;
        *reinterpret_cast<float4*>(ddb + off) = o;
    }
}

extern "C" void kernel_launch(void* const* d_in, const int* in_sizes, int n_in,
                              void* d_out, int out_size)
{
    const float* guid   = (const float*)d_in[0];
    const float* blur   = (const float*)d_in[1];
    const float* sparse = (const float*)d_in[2];
    float*       out    = (float*)d_out;

    static int attr_done = 0;
    if (!attr_done) {
        cudaFuncSetAttribute(double_kernel,
                             cudaFuncAttributeMaxDynamicSharedMemorySize,
                             SMEM_BYTES);
        attr_done = 1;
    }

    init_kernel<<<NPIX / 4 / 256, 256>>>(blur, sparse);
    rpre_kernel<<<CC * 512, 64>>>(guid);

    // d0 in d_bufA; each launch performs 2 CSPN steps. 8 launches = 16 steps.
    for (int i = 0; i < NSTEPS; i++) {
        float* dst_ext = (i == NSTEPS - 1) ? out : nullptr;
        double_kernel<<<GRID_I, 256, SMEM_BYTES>>>(i & 1, dst_ext, guid, sparse);
    }
}

// round 16
// speedup vs baseline: 1.1007x; 1.1007x over previous
#include <cuda_runtime.h>
#include <cstdint>
#include <math.h>

#define BB 8
#define CC 8
#define HH 256
#define WW 512
#define PLANE (HH*WW)
#define NPIX (BB*PLANE)
#define OUTH 8
#define D1R (OUTH+2)
#define IR  (OUTH+4)
#define TX 128
#define SROW 136
#define GRID_I (BB*(HH/OUTH)*(WW/TX))       /* 1024 */
#define NSTEPS 8
#define FULLMASK 0xffffffffu

#define SG  (CC*IR*SROW)
#define SD  (IR*SROW)
#define SD1 (D1R*SROW)
#define SMEM_FLOATS (16 + SG + SD + SD1)
#define SMEM_BYTES (SMEM_FLOATS*4)          /* 64,256 B -> 3 CTAs/SM */

// Scratch (allocation-free).
__device__ float d_bufA[NPIX];
__device__ float d_bufB[NPIX];
__device__ float r_buf[(size_t)BB*CC*PLANE];   // 1/(3x3 sum |g|), iter-invariant

// ---------------------------------------------------------------------------
__global__ __launch_bounds__(256) void init_kernel(
    const float* __restrict__ blur,
    const float* __restrict__ sparse)
{
    const int i = blockIdx.x * 256 + threadIdx.x;
    const float4 s = reinterpret_cast<const float4*>(sparse)[i];
    float4 v       = reinterpret_cast<const float4*>(blur)[i];
    v.x = (s.x > 0.f) ? s.x : v.x;
    v.y = (s.y > 0.f) ? s.y : v.y;
    v.z = (s.z > 0.f) ? s.z : v.z;
    v.w = (s.w > 0.f) ? s.w : v.w;
    reinterpret_cast<float4*>(d_bufA)[i] = v;
}

// ---------------------------------------------------------------------------
// Pre-pass (once): r = 1/(3x3 in-image sum of |guid|).
// ---------------------------------------------------------------------------
__global__ __launch_bounds__(64) void rpre_kernel(const float* __restrict__ guid)
{
    const int lane  = threadIdx.x & 31;
    const int warp  = threadIdx.x >> 5;
    const int c     = blockIdx.x >> 9;
    const int inner = blockIdx.x & 511;
    const int band  = inner >> 1;
    const int chunk = inner & 1;
    const int x0    = chunk * 256 + warp * 128 + lane * 4;
    const int b     = (band * 8) / HH;
    const int y0    = (band * 8) % HH;

    const float* gin  = guid  + ((size_t)(b * CC + c)) * PLANE;
    float*       rout = r_buf + ((size_t)(b * CC + c)) * PLANE;

    float4 rsp = make_float4(0.f,0.f,0.f,0.f);
    float4 rsc = make_float4(0.f,0.f,0.f,0.f);

    #pragma unroll
    for (int i = 0; i < 10; i++) {
        const int  ry    = y0 - 1 + i;
        const bool valid = (ry >= 0) && (ry < HH);

        float4 ga = make_float4(0.f,0.f,0.f,0.f);
        if (valid) {
            const float4 gv = *reinterpret_cast<const float4*>(gin + (size_t)ry * WW + x0);
            ga.x = fabsf(gv.x); ga.y = fabsf(gv.y);
            ga.z = fabsf(gv.z); ga.w = fabsf(gv.w);
        }
        float gm1 = __shfl_up_sync  (FULLMASK, ga.w, 1);
        float gp4 = __shfl_down_sync(FULLMASK, ga.x, 1);
        if (lane == 0)  gm1 = (valid && x0 > 0)      ? fabsf(gin[(size_t)ry * WW + x0 - 1]) : 0.f;
        if (lane == 31) gp4 = (valid && x0 + 4 < WW) ? fabsf(gin[(size_t)ry * WW + x0 + 4]) : 0.f;

        float4 rsn;
        {
            const float s01 = ga.x + ga.y, s12 = ga.y + ga.z, s23 = ga.z + ga.w;
            rsn.x = gm1 + s01; rsn.y = s01 + ga.z;
            rsn.z = s12 + ga.w; rsn.w = s23 + gp4;
        }
        if (i >= 2) {
            const int yo = y0 + i - 2;
            float4 rv;
            rv.x = 1.0f / (rsp.x + rsc.x + rsn.x);
            rv.y = 1.0f / (rsp.y + rsc.y + rsn.y);
            rv.z = 1.0f / (rsp.z + rsc.z + rsn.z);
            rv.w = 1.0f / (rsp.w + rsc.w + rsn.w);
            *reinterpret_cast<float4*>(rout + (size_t)yo * WW + x0) = rv;
        }
        rsp = rsc; rsc = rsn;
    }
}

// ---------------------------------------------------------------------------
// TWO CSPN steps per launch; numerator-only phases (denominators precomputed
// in r_buf, PREFETCHED per task into a register array before the channel loop
// so the LDG latency is covered by channel-0..1 compute).
// ---------------------------------------------------------------------------
__global__ __launch_bounds__(256, 3) void double_kernel(
    int src_sel,
    float* __restrict__ dst_ext,
    const float* __restrict__ guid,
    const float* __restrict__ sparse)
{
    extern __shared__ float smem[];
    float* sg  = smem + 16;
    float* sdm = sg + SG;
    float* sd1 = sdm + SD;
    const unsigned mbar = (unsigned)__cvta_generic_to_shared(smem);

    const int tid  = threadIdx.x;
    const int lane = tid & 31;
    const int wid  = tid >> 5;
    const int bid  = blockIdx.x;
    const int xc   = bid & 3;
    const int yb   = (bid >> 2) & 31;
    const int b    = bid >> 7;
    const int x0   = xc * TX;
    const int y0   = yb * OUTH;

    const float* dsrc  = src_sel ? d_bufB : d_bufA;
    float*       ddst  = dst_ext ? dst_ext : (src_sel ? d_bufA : d_bufB);
    const float* dsb   = dsrc   + (size_t)b * PLANE;
    const float* spb   = sparse + (size_t)b * PLANE;
    float*       ddb   = ddst   + (size_t)b * PLANE;
    const float* gbase = guid   + ((size_t)(b * CC)) * PLANE;
    const float* rbase = r_buf  + ((size_t)(b * CC)) * PLANE;

    const bool left  = (x0 == 0);
    const bool right = (x0 + TX >= WW);
    const int  src_c0  = left ? 0 : (x0 - 4);
    const int  dst_off = left ? 4 : 0;
    const unsigned cpy_b = (left || right) ? 528u : 544u;
    const int top = (y0 == 0)          ? 2 : 0;
    const int bot = (y0 + OUTH == HH)  ? 2 : 0;

    if (tid == 0)
        asm volatile("mbarrier.init.shared.b64 [%0], %1;" :: "r"(mbar), "r"(1u) : "memory");
    __syncthreads();
    if (tid == 0) {
        const unsigned tx = (unsigned)(CC * (IR - top - bot) + IR) * cpy_b;
        asm volatile("mbarrier.arrive.expect_tx.shared.b64 _, [%0], %1;"
                     :: "r"(mbar), "r"(tx) : "memory");
    }
    __syncthreads();

    if (tid < (CC + 1) * IR) {
        const int cc = tid / IR;
        const int r  = tid % IR;
        const int ry = y0 - 2 + r;
        if (cc < CC) {
            if (ry >= 0 && ry < HH) {
                const float* src = gbase + (size_t)cc * PLANE + (size_t)ry * WW + src_c0;
                const unsigned dsm_ = (unsigned)__cvta_generic_to_shared(
                                          sg + (cc * IR + r) * SROW + dst_off);
                asm volatile(
                    "cp.async.bulk.shared::cta.global.mbarrier::complete_tx::bytes "
                    "[%0], [%1], %2, [%3];"
                    :: "r"(dsm_), "l"(src), "r"(cpy_b), "r"(mbar) : "memory");
            }
        } else {
            const int ryc = (ry < 0) ? 0 : ((ry >= HH) ? (HH - 1) : ry);
            const float* src = dsb + (size_t)ryc * WW + src_c0;
            const unsigned dsm_ = (unsigned)__cvta_generic_to_shared(
                                      sdm + r * SROW + dst_off);
            asm volatile(
                "cp.async.bulk.shared::cta.global.mbarrier::complete_tx::bytes "
                "[%0], [%1], %2, [%3];"
                :: "r"(dsm_), "l"(src), "r"(cpy_b), "r"(mbar) : "memory");
        }
    }

    if (top + bot) {
        const int per = (top + bot) * 34;
        const int nz  = CC * per;
        for (int idx = tid; idx < nz; idx += 256) {
            const int ch  = idx / per;
            const int rem = idx - ch * per;
            const int ri  = rem / 34;
            const int j   = rem - ri * 34;
            const int r   = (ri < top) ? ri : (IR - bot + (ri - top));
            *reinterpret_cast<float4*>(sg + (ch * IR + r) * SROW + 4 * j) =
                make_float4(0.f, 0.f, 0.f, 0.f);
        }
    }
    if ((left || right) && tid < (CC + 1) * IR) {
        const int zc = left ? 0 : 132;
        const int cc = tid / IR;
        const int r  = tid % IR;
        float* p = (cc < CC) ? (sg + (cc * IR + r) * SROW + zc)
                             : (sdm + r * SROW + zc);
        *reinterpret_cast<float4*>(p) = make_float4(0.f, 0.f, 0.f, 0.f);
    }

    {
        unsigned done;
        asm volatile(
            "{\n\t.reg .pred p;\n\t"
            "mbarrier.try_wait.parity.acquire.cta.shared::cta.b64 p, [%1], %2;\n\t"
            "selp.b32 %0, 1, 0, p;\n\t}"
            : "=r"(done) : "r"(mbar), "r"(0u) : "memory");
        if (!done) {
            asm volatile(
                "{\n\t.reg .pred P1;\n\t"
                "WAIT_LOOP_%=:\n\t"
                "mbarrier.try_wait.parity.acquire.cta.shared::cta.b64 P1, [%0], %1, 0x989680;\n\t"
                "@P1 bra.uni WAIT_DONE_%=;\n\t"
                "bra.uni WAIT_LOOP_%=;\n\t"
                "WAIT_DONE_%=:\n\t}"
                :: "r"(mbar), "r"(0u) : "memory");
        }
    }
    __syncthreads();

    const int  sc   = 4 + lane * 4;
    const bool is_l = (lane == 0);
    const bool is_r = (lane == 31);

    // ================= PHASE 1 ==============================================
    #pragma unroll
    for (int r1 = wid; r1 < D1R; r1 += 8) {
        const int  yrow = y0 - 1 + r1;
        const bool rv   = (yrow >= 0) && (yrow < HH);
        const int  yrc  = (yrow < 0) ? 0 : ((yrow >= HH) ? (HH - 1) : yrow);

        // prefetch ALL channel reciprocals first (8 independent LDG.128)
        float4 rws[CC];
        #pragma unroll
        for (int ch = 0; ch < CC; ch++)
            rws[ch] = *reinterpret_cast<const float4*>(
                          rbase + (size_t)ch * PLANE + (size_t)yrc * WW + x0 + lane * 4);

        float4 dv[3]; float dlf[3], drt[3];
        #pragma unroll
        for (int rr = 0; rr < 3; rr++) {
            const float* dp = sdm + (r1 + rr) * SROW;
            dv[rr] = *reinterpret_cast<const float4*>(dp + sc);
            const float up = __shfl_up_sync  (FULLMASK, dv[rr].w, 1);
            const float dn = __shfl_down_sync(FULLMASK, dv[rr].x, 1);
            dlf[rr] = is_l ? dp[3]   : up;
            drt[rr] = is_r ? dp[132] : dn;
        }
        float mx0 = 0.f, mx1 = 0.f, mx2 = 0.f, mx3 = 0.f;
        #pragma unroll
        for (int ch = 0; ch < CC; ch++) {
            const float* gb = sg + ch * IR * SROW;
            float n0=0.f,n1=0.f,n2=0.f,n3=0.f;
            #pragma unroll
            for (int rr = 0; rr < 3; rr++) {
                const float* gp = gb + (r1 + rr) * SROW;
                const float4 gv = *reinterpret_cast<const float4*>(gp + sc);
                const float gup = __shfl_up_sync  (FULLMASK, gv.w, 1);
                const float gdn = __shfl_down_sync(FULLMASK, gv.x, 1);
                const float gl  = is_l ? gp[3]   : gup;
                const float gr_ = is_r ? gp[132] : gdn;
                const float ul = fabsf(gl)   * dlf[rr];
                const float u0 = fabsf(gv.x) * dv[rr].x;
                const float u1 = fabsf(gv.y) * dv[rr].y;
                const float u2 = fabsf(gv.z) * dv[rr].z;
                const float u3 = fabsf(gv.w) * dv[rr].w;
                const float ur = fabsf(gr_)  * drt[rr];
                const float t01 = u0 + u1, t12 = u1 + u2, t23 = u2 + u3;
                n0 += ul + t01; n1 += t01 + u2; n2 += t12 + u3; n3 += t23 + ur;
            }
            mx0 = fmaxf(mx0, n0 * rws[ch].x);
            mx1 = fmaxf(mx1, n1 * rws[ch].y);
            mx2 = fmaxf(mx2, n2 * rws[ch].z);
            mx3 = fmaxf(mx3, n3 * rws[ch].w);
        }
        const float4 s = *reinterpret_cast<const float4*>(
                             spb + (size_t)yrc * WW + x0 + lane * 4);
        float4 o;
        o.x = rv ? ((s.x > 0.f) ? s.x : mx0) : 0.f;
        o.y = rv ? ((s.y > 0.f) ? s.y : mx1) : 0.f;
        o.z = rv ? ((s.z > 0.f) ? s.z : mx2) : 0.f;
        o.w = rv ? ((s.w > 0.f) ? s.w : mx3) : 0.f;
        *reinterpret_cast<float4*>(sd1 + r1 * SROW + sc) = o;
    }

    // ---- tail: d1 edge cols (smem cols 3 and 132) — inline e, negligible ----
    if (tid < 2 * D1R) {
        const int r1   = tid >> 1;
        const int colc = (tid & 1) ? 132 : 3;
        const int  yrow = y0 - 1 + r1;
        const bool rv   = (yrow >= 0) && (yrow < HH);
        const int  yrc  = (yrow < 0) ? 0 : ((yrow >= HH) ? (HH - 1) : yrow);
        const int  gx   = x0 - 4 + colc;
        const bool xv   = (gx >= 0) && (gx < WW);

        float mx = 0.f;
        #pragma unroll
        for (int ch = 0; ch < CC; ch++) {
            const float* gb = sg + ch * IR * SROW;
            float n = 0.f, e = 0.f;
            #pragma unroll
            for (int rr = 0; rr < 3; rr++) {
                const float* gp = gb  + (r1 + rr) * SROW;
                const float* dp = sdm + (r1 + rr) * SROW;
                #pragma unroll
                for (int dc = -1; dc <= 1; dc++) {
                    const float g = fabsf(gp[colc + dc]);
                    e += g;
                    n += g * dp[colc + dc];
                }
            }
            mx = fmaxf(mx, __fdividef(n, e));
        }
        const int gxc = (gx < 0) ? 0 : ((gx >= WW) ? (WW - 1) : gx);
        const float s = spb[(size_t)yrc * WW + gxc];
        sd1[r1 * SROW + colc] = (rv && xv) ? ((s > 0.f) ? s : mx) : 0.f;
    }
    __syncthreads();

    // ================= PHASE 2 ==============================================
    {
        const int k = wid;

        float4 rws[CC];
        #pragma unroll
        for (int ch = 0; ch < CC; ch++)
            rws[ch] = *reinterpret_cast<const float4*>(
                          rbase + (size_t)ch * PLANE + (size_t)(y0 + k) * WW + x0 + lane * 4);

        float4 dv[3]; float dlf[3], drt[3];
        #pragma unroll
        for (int rr = 0; rr < 3; rr++) {
            const float* dp = sd1 + (k + rr) * SROW;
            dv[rr] = *reinterpret_cast<const float4*>(dp + sc);
            const float up = __shfl_up_sync  (FULLMASK, dv[rr].w, 1);
            const float dn = __shfl_down_sync(FULLMASK, dv[rr].x, 1);
            dlf[rr] = is_l ? dp[3]   : up;
            drt[rr] = is_r ? dp[132] : dn;
        }
        float mx0 = 0.f, mx1 = 0.f, mx2 = 0.f, mx3 = 0.f;
        #pragma unroll
        for (int ch = 0; ch < CC; ch++) {
            const float* gb = sg + ch * IR * SROW;
            float n0=0.f,n1=0.f,n2=0.f,n3=0.f;
            #pragma unroll
            for (int rr = 0; rr < 3; rr++) {
                const float* gp = gb + (k + 1 + rr) * SROW;
                const float4 gv = *reinterpret_cast<const float4*>(gp + sc);
                const float gup = __shfl_up_sync  (FULLMASK, gv.w, 1);
                const float gdn = __shfl_down_sync(FULLMASK, gv.x, 1);
                const float gl  = is_l ? gp[3]   : gup;
                const float gr_ = is_r ? gp[132] : gdn;
                const float ul = fabsf(gl)   * dlf[rr];
                const float u0 = fabsf(gv.x) * dv[rr].x;
                const float u1 = fabsf(gv.y) * dv[rr].y;
                const float u2 = fabsf(gv.z) * dv[rr].z;
                const float u3 = fabsf(gv.w) * dv[rr].w;
                const float ur = fabsf(gr_)  * drt[rr];
                const float t01 = u0 + u1, t12 = u1 + u2, t23 = u2 + u3;
                n0 += ul + t01; n1 += t01 + u2; n2 += t12 + u3; n3 += t23 + ur;
            }
            mx0 = fmaxf(mx0, n0 * rws[ch].x);
            mx1 = fmaxf(mx1, n1 * rws[ch].y);
            mx2 = fmaxf(mx2, n2 * rws[ch].z);
            mx3 = fmaxf(mx3, n3 * rws[ch].w);
        }
        const size_t off = (size_t)(y0 + k) * WW + x0 + lane * 4;
        const float4 s = *reinterpret_cast<const float4*>(spb + off);
        float4 o;
        o.x = (s.x > 0.f) ? s.x : mx0;
        o.y = (s.y > 0.f) ? s.y : mx1;
        o.z = (s.z > 0.f) ? s.z : mx2;
        o.w = (s.w > 0.f) ? s.w : mx3;
        *reinterpret_cast<float4*>(ddb + off) = o;
    }
}

extern "C" void kernel_launch(void* const* d_in, const int* in_sizes, int n_in,
                              void* d_out, int out_size)
{
    const float* guid   = (const float*)d_in[0];
    const float* blur   = (const float*)d_in[1];
    const float* sparse = (const float*)d_in[2];
    float*       out    = (float*)d_out;

    static int attr_done = 0;
    if (!attr_done) {
        cudaFuncSetAttribute(double_kernel,
                             cudaFuncAttributeMaxDynamicSharedMemorySize,
                             SMEM_BYTES);
        attr_done = 1;
    }

    init_kernel<<<NPIX / 4 / 256, 256>>>(blur, sparse);
    rpre_kernel<<<CC * 512, 64>>>(guid);

    for (int i = 0; i < NSTEPS; i++) {
        float* dst_ext = (i == NSTEPS - 1) ? out : nullptr;
        double_kernel<<<GRID_I, 256, SMEM_BYTES>>>(i & 1, dst_ext, guid, sparse);
    }
}